// round 1
// baseline (speedup 1.0000x reference)
#include <cuda_runtime.h>
#include <math.h>

#define BB  256
#define GG  2048
#define FF  128
#define RNN 512
#define KK  128

// Scratch (no allocation allowed) ------------------------------------------
__device__ float g_scorer[BB * FF];   // scorer / ||scorer||, per batch
__device__ float g_scores[BB * GG];   // scores (incl. mask)
__device__ float g_tvals [BB * KK];   // tanh(topk values), sorted desc
__device__ int   g_tidx  [BB * KK];   // topk indices, sorted desc

// --------------------------------------------------------------------------
// K1: scorer[b,f] = tanh(h_t[b,:] @ W[:,f] + bias[f]) / ||tanh(...)||_2
// --------------------------------------------------------------------------
__global__ void k1_scorer(const float* __restrict__ h_t,
                          const float* __restrict__ W,
                          const float* __restrict__ bmap) {
    int b = blockIdx.x, f = threadIdx.x;     // 128 threads
    __shared__ float h[RNN];
    __shared__ float red[FF];
    for (int i = f; i < RNN; i += FF) h[i] = h_t[b * RNN + i];
    __syncthreads();
    float acc = bmap[f];
#pragma unroll 8
    for (int r = 0; r < RNN; ++r) acc = fmaf(h[r], W[r * FF + f], acc);
    float s = tanhf(acc);
    red[f] = s * s;
    __syncthreads();
    for (int o = FF / 2; o > 0; o >>= 1) {
        if (f < o) red[f] += red[f + o];
        __syncthreads();
    }
    g_scorer[b * FF + f] = s * rsqrtf(red[0]);
}

// --------------------------------------------------------------------------
// K2: scores[b,g] = node_embs[b,g,:] . scorer[b,:] + mask[b,g]
//     warp per (b,g): one float4 per lane = 512B coalesced row
// --------------------------------------------------------------------------
__global__ void k2_scores(const float* __restrict__ ne,
                          const float* __restrict__ mask) {
    int b = blockIdx.x;
    int gbase = blockIdx.y * 64;             // 64 g-rows per block
    __shared__ float4 sc[FF / 4];
    int tid = threadIdx.x;                   // 256 threads
    if (tid < FF / 4)
        sc[tid] = reinterpret_cast<const float4*>(g_scorer + b * FF)[tid];
    __syncthreads();
    int warp = tid >> 5, lane = tid & 31;
    float4 s = sc[lane];
    const float4* base = reinterpret_cast<const float4*>(ne) + (size_t)b * GG * (FF / 4);
#pragma unroll
    for (int it = 0; it < 8; ++it) {
        int g = gbase + it * 8 + warp;
        float4 v = base[(size_t)g * (FF / 4) + lane];
        float d = v.x * s.x + v.y * s.y + v.z * s.z + v.w * s.w;
#pragma unroll
        for (int o = 16; o > 0; o >>= 1) d += __shfl_xor_sync(0xffffffffu, d, o);
        if (lane == 0) g_scores[b * GG + g] = d + mask[b * GG + g];
    }
}

// --------------------------------------------------------------------------
// K3: per-batch logsumexp + full bitonic sort (desc) of 2048 packed keys,
//     emit top-128 (tanh(val), idx) and policy score.
// Key = sortable(value) << 32 | ~index  -> descending sort gives exactly
// jax.lax.top_k ordering (lower index wins ties).
// --------------------------------------------------------------------------
__device__ __forceinline__ unsigned f2u(float f) {
    unsigned u = __float_as_uint(f);
    return (u & 0x80000000u) ? ~u : (u | 0x80000000u);
}
__device__ __forceinline__ float u2f(unsigned u) {
    unsigned b = (u & 0x80000000u) ? (u & 0x7FFFFFFFu) : ~u;
    return __uint_as_float(b);
}

__global__ void k3_topk(float* __restrict__ policy_out) {
    int b = blockIdx.x, tid = threadIdx.x;   // 512 threads
    __shared__ float s[GG];
    __shared__ unsigned long long key[GG];
    __shared__ float rbuf[512];

    for (int i = tid; i < GG; i += 512) s[i] = g_scores[b * GG + i];
    __syncthreads();

    // max
    float m = -INFINITY;
    for (int i = tid; i < GG; i += 512) m = fmaxf(m, s[i]);
    rbuf[tid] = m; __syncthreads();
    for (int o = 256; o > 0; o >>= 1) {
        if (tid < o) rbuf[tid] = fmaxf(rbuf[tid], rbuf[tid + o]);
        __syncthreads();
    }
    float smax = rbuf[0];
    __syncthreads();

    // sum exp
    float sum = 0.f;
    for (int i = tid; i < GG; i += 512) sum += expf(s[i] - smax);
    rbuf[tid] = sum; __syncthreads();
    for (int o = 256; o > 0; o >>= 1) {
        if (tid < o) rbuf[tid] += rbuf[tid + o];
        __syncthreads();
    }
    float lse = smax + logf(rbuf[0]);
    __syncthreads();

    // pack keys
    for (int i = tid; i < GG; i += 512)
        key[i] = ((unsigned long long)f2u(s[i]) << 32) | (unsigned)(~(unsigned)i);
    __syncthreads();

    // bitonic sort, descending
    for (unsigned k = 2; k <= GG; k <<= 1) {
        for (unsigned j = k >> 1; j > 0; j >>= 1) {
            for (int i = tid; i < GG; i += 512) {
                unsigned ixj = (unsigned)i ^ j;
                if (ixj > (unsigned)i) {
                    unsigned long long a = key[i], c = key[ixj];
                    bool dir = ((i & k) == 0);
                    if ((a < c) == dir) { key[i] = c; key[ixj] = a; }
                }
            }
            __syncthreads();
        }
    }

    float v = 0.f;
    if (tid < KK) {
        unsigned long long kk = key[tid];
        v = u2f((unsigned)(kk >> 32));
        unsigned low = (unsigned)kk;
        g_tvals[b * KK + tid] = tanhf(v);
        g_tidx [b * KK + tid] = (int)(~low);
    }
    rbuf[tid] = (tid < KK) ? v : 0.f;
    __syncthreads();
    for (int o = 256; o > 0; o >>= 1) {
        if (tid < o) rbuf[tid] += rbuf[tid + o];
        __syncthreads();
    }
    if (tid == 0) policy_out[b] = rbuf[0] * (1.0f / KK) - lse;
}

// --------------------------------------------------------------------------
// K4: out[b,f,k] = node_embs[b, idx[b,k], f] * tanh(val[b,k])
//     gather rows coalesced into padded smem tile, write transposed.
//     Two 64-row halves to stay within 48KB static smem.
// --------------------------------------------------------------------------
__global__ void k4_gather(const float* __restrict__ ne, float* __restrict__ out) {
    int b = blockIdx.x, tid = threadIdx.x;   // 256 threads
    __shared__ float tile[64 * 129];
    __shared__ float tv[KK];
    __shared__ int   ti[KK];
    if (tid < KK) { tv[tid] = g_tvals[b * KK + tid]; ti[tid] = g_tidx[b * KK + tid]; }
    __syncthreads();
    const float* base = ne + (size_t)b * GG * FF;
    float* ob = out + (size_t)b * FF * KK;
    for (int half = 0; half < 2; ++half) {
        int k0 = half * 64;
        for (int i = tid; i < 64 * FF; i += 256) {
            int k = i >> 7, f = i & 127;
            tile[k * 129 + f] = base[(size_t)ti[k0 + k] * FF + f] * tv[k0 + k];
        }
        __syncthreads();
        for (int i = tid; i < FF * 64; i += 256) {
            int f = i >> 6, k = i & 63;
            ob[f * KK + k0 + k] = tile[k * 129 + f];
        }
        __syncthreads();
    }
}

// --------------------------------------------------------------------------
extern "C" void kernel_launch(void* const* d_in, const int* in_sizes, int n_in,
                              void* d_out, int out_size) {
    const float* node_embs = (const float*)d_in[0];
    const float* mask      = (const float*)d_in[1];
    const float* h_t       = (const float*)d_in[2];
    const float* W_map     = (const float*)d_in[3];
    const float* b_map     = (const float*)d_in[4];
    float* out    = (float*)d_out;
    float* policy = out + (size_t)BB * FF * KK;   // outputs concatenated: [B,F,K] then [B]

    k1_scorer<<<BB, FF>>>(h_t, W_map, b_map);
    k2_scores<<<dim3(BB, GG / 64), 256>>>(node_embs, mask);
    k3_topk<<<BB, 512>>>(policy);
    k4_gather<<<BB, 256>>>(node_embs, out);
}

// round 2
// speedup vs baseline: 1.3929x; 1.3929x over previous
#include <cuda_runtime.h>
#include <math.h>

#define BB  256
#define GG  2048
#define FF  128
#define RNN 512
#define KK  128

// Scratch (no allocation allowed) ------------------------------------------
__device__ float g_scorer[BB * FF];   // scorer / ||scorer||, per batch
__device__ float g_scores[BB * GG];   // scores (incl. mask)
__device__ float g_tvals [BB * KK];   // tanh(topk values), sorted desc
__device__ int   g_tidx  [BB * KK];   // topk indices, sorted desc

// --------------------------------------------------------------------------
// K1: scorer[b,f] = tanh(h_t[b,:] @ W[:,f] + bias[f]) / ||tanh(...)||_2
// --------------------------------------------------------------------------
__global__ void k1_scorer(const float* __restrict__ h_t,
                          const float* __restrict__ W,
                          const float* __restrict__ bmap) {
    int b = blockIdx.x, f = threadIdx.x;     // 128 threads
    __shared__ float h[RNN];
    __shared__ float red[FF];
    for (int i = f; i < RNN; i += FF) h[i] = h_t[b * RNN + i];
    __syncthreads();
    float acc = bmap[f];
#pragma unroll 8
    for (int r = 0; r < RNN; ++r) acc = fmaf(h[r], W[r * FF + f], acc);
    float s = tanhf(acc);
    red[f] = s * s;
    __syncthreads();
    for (int o = FF / 2; o > 0; o >>= 1) {
        if (f < o) red[f] += red[f + o];
        __syncthreads();
    }
    g_scorer[b * FF + f] = s * rsqrtf(red[0]);
}

// --------------------------------------------------------------------------
// K2: scores[b,g] = node_embs[b,g,:] . scorer[b,:] + mask[b,g]
//     warp per row, 4 independent rows in flight per warp for MLP
// --------------------------------------------------------------------------
__global__ void k2_scores(const float* __restrict__ ne,
                          const float* __restrict__ mask) {
    int b = blockIdx.x;
    int gbase = blockIdx.y * 64;             // 64 g-rows per block
    __shared__ float4 sc[FF / 4];
    int tid = threadIdx.x;                   // 256 threads
    if (tid < FF / 4)
        sc[tid] = reinterpret_cast<const float4*>(g_scorer + b * FF)[tid];
    __syncthreads();
    int warp = tid >> 5, lane = tid & 31;
    float4 s = sc[lane];
    const float4* base = reinterpret_cast<const float4*>(ne) + (size_t)b * GG * (FF / 4);
    int g0 = gbase + warp * 8;
#pragma unroll
    for (int half = 0; half < 2; ++half) {
        float d0, d1, d2, d3;
        {
            float4 v0 = base[(size_t)(g0 + half * 4 + 0) * (FF / 4) + lane];
            float4 v1 = base[(size_t)(g0 + half * 4 + 1) * (FF / 4) + lane];
            float4 v2 = base[(size_t)(g0 + half * 4 + 2) * (FF / 4) + lane];
            float4 v3 = base[(size_t)(g0 + half * 4 + 3) * (FF / 4) + lane];
            d0 = v0.x * s.x + v0.y * s.y + v0.z * s.z + v0.w * s.w;
            d1 = v1.x * s.x + v1.y * s.y + v1.z * s.z + v1.w * s.w;
            d2 = v2.x * s.x + v2.y * s.y + v2.z * s.z + v2.w * s.w;
            d3 = v3.x * s.x + v3.y * s.y + v3.z * s.z + v3.w * s.w;
        }
#pragma unroll
        for (int o = 16; o > 0; o >>= 1) {
            d0 += __shfl_xor_sync(0xffffffffu, d0, o);
            d1 += __shfl_xor_sync(0xffffffffu, d1, o);
            d2 += __shfl_xor_sync(0xffffffffu, d2, o);
            d3 += __shfl_xor_sync(0xffffffffu, d3, o);
        }
        if (lane == 0) {
            int g = g0 + half * 4;
            const float* mb = mask + b * GG + g;
            float* ob = g_scores + b * GG + g;
            ob[0] = d0 + mb[0];
            ob[1] = d1 + mb[1];
            ob[2] = d2 + mb[2];
            ob[3] = d3 + mb[3];
        }
    }
}

// --------------------------------------------------------------------------
// K3: per-batch logsumexp + exact radix-select of top-128 64-bit keys
//     key = sortable(value)<<32 | ~index  (all keys distinct)
//     then bitonic sort of just the 128 selected keys.
// --------------------------------------------------------------------------
__device__ __forceinline__ unsigned f2u(float f) {
    unsigned u = __float_as_uint(f);
    return (u & 0x80000000u) ? ~u : (u | 0x80000000u);
}
__device__ __forceinline__ float u2f(unsigned u) {
    unsigned b = (u & 0x80000000u) ? (u & 0x7FFFFFFFu) : ~u;
    return __uint_as_float(b);
}

__global__ void k3_topk(float* __restrict__ policy_out) {
    int b = blockIdx.x, tid = threadIdx.x;   // 512 threads, 4 elems/thread
    __shared__ unsigned hist[256];
    __shared__ unsigned long long top[KK];
    __shared__ float rbuf[512];
    __shared__ unsigned sel_d, sel_sub, cnt_;

    // load scores into registers
    float v[4];
    unsigned long long kreg[4];
#pragma unroll
    for (int j = 0; j < 4; ++j) v[j] = g_scores[b * GG + tid + j * 512];

    // max reduce
    float m = fmaxf(fmaxf(v[0], v[1]), fmaxf(v[2], v[3]));
    rbuf[tid] = m; __syncthreads();
    for (int o = 256; o > 0; o >>= 1) {
        if (tid < o) rbuf[tid] = fmaxf(rbuf[tid], rbuf[tid + o]);
        __syncthreads();
    }
    float smax = rbuf[0];
    __syncthreads();

    // sum exp reduce
    float sum = expf(v[0] - smax) + expf(v[1] - smax) +
                expf(v[2] - smax) + expf(v[3] - smax);
    rbuf[tid] = sum; __syncthreads();
    for (int o = 256; o > 0; o >>= 1) {
        if (tid < o) rbuf[tid] += rbuf[tid + o];
        __syncthreads();
    }
    float lse = smax + logf(rbuf[0]);
    __syncthreads();

    // pack keys (registers)
#pragma unroll
    for (int j = 0; j < 4; ++j)
        kreg[j] = ((unsigned long long)f2u(v[j]) << 32) |
                  (unsigned)(~(unsigned)(tid + j * 512));

    // radix select: find exact 128th-largest key
    unsigned long long prefix = 0;
    unsigned kneed = KK;
    for (int shift = 56; shift >= 0; shift -= 8) {
        unsigned long long mask_hi = (shift == 56) ? 0ULL : (~0ULL << (shift + 8));
        for (int i = tid; i < 256; i += 512) hist[i] = 0;
        __syncthreads();
#pragma unroll
        for (int j = 0; j < 4; ++j) {
            if ((kreg[j] & mask_hi) == prefix)
                atomicAdd(&hist[(unsigned)(kreg[j] >> shift) & 0xFFu], 1u);
        }
        __syncthreads();
        // inclusive suffix sum over 256 bins
        for (int off = 1; off < 256; off <<= 1) {
            unsigned t_;
            if (tid < 256) t_ = hist[tid] + ((tid + off < 256) ? hist[tid + off] : 0u);
            __syncthreads();
            if (tid < 256) hist[tid] = t_;
            __syncthreads();
        }
        // d* = max d with suffix(d) >= kneed
        if (tid < 256) {
            if (hist[tid] >= kneed && (tid == 255 || hist[tid + 1] < kneed)) {
                sel_d = (unsigned)tid;
                sel_sub = (tid == 255) ? 0u : hist[tid + 1];
            }
        }
        __syncthreads();
        prefix |= ((unsigned long long)sel_d) << shift;
        kneed -= sel_sub;
        __syncthreads();
    }

    // collect the exactly-128 keys >= prefix
    if (tid == 0) cnt_ = 0;
    __syncthreads();
#pragma unroll
    for (int j = 0; j < 4; ++j) {
        if (kreg[j] >= prefix) {
            unsigned p = atomicAdd(&cnt_, 1u);
            top[p] = kreg[j];
        }
    }
    __syncthreads();

    // bitonic sort 128 keys descending
    for (unsigned kk = 2; kk <= KK; kk <<= 1) {
        for (unsigned j = kk >> 1; j > 0; j >>= 1) {
            if (tid < KK) {
                unsigned i = (unsigned)tid, ixj = i ^ j;
                if (ixj > i) {
                    unsigned long long a = top[i], c = top[ixj];
                    bool dir = ((i & kk) == 0);
                    if ((a < c) == dir) { top[i] = c; top[ixj] = a; }
                }
            }
            __syncthreads();
        }
    }

    // emit
    float val = 0.f;
    if (tid < KK) {
        unsigned long long kk = top[tid];
        val = u2f((unsigned)(kk >> 32));
        g_tvals[b * KK + tid] = tanhf(val);
        g_tidx [b * KK + tid] = (int)(~(unsigned)kk);
    }
    rbuf[tid] = (tid < KK) ? val : 0.f;
    __syncthreads();
    for (int o = 256; o > 0; o >>= 1) {
        if (tid < o) rbuf[tid] += rbuf[tid + o];
        __syncthreads();
    }
    if (tid == 0) policy_out[b] = rbuf[0] * (1.0f / KK) - lse;
}

// --------------------------------------------------------------------------
// K4: out[b,f,k] = node_embs[b, idx[b,k], f] * tanh(val[b,k])
//     4 blocks per batch (32 k-rows each), padded smem transpose tile
// --------------------------------------------------------------------------
__global__ void k4_gather(const float* __restrict__ ne, float* __restrict__ out) {
    int b = blockIdx.x, kq = blockIdx.y;     // quarter index 0..3
    int tid = threadIdx.x;                   // 256 threads
    __shared__ float tile[32 * 129];
    __shared__ float tv[32];
    __shared__ int   ti[32];
    if (tid < 32) {
        tv[tid] = g_tvals[b * KK + kq * 32 + tid];
        ti[tid] = g_tidx [b * KK + kq * 32 + tid];
    }
    __syncthreads();
    const float* base = ne + (size_t)b * GG * FF;
    float* ob = out + (size_t)b * FF * KK + kq * 32;
    // load: 32 rows x 128 floats, coalesced gmem reads, conflict-free STS
#pragma unroll
    for (int it = 0; it < 16; ++it) {
        int i = tid + it * 256;
        int k = i >> 7, f = i & 127;
        tile[k * 129 + f] = base[(size_t)ti[k] * FF + f] * tv[k];
    }
    __syncthreads();
    // write transposed: warp reads stride-129 (conflict-free), writes 128B runs
#pragma unroll
    for (int it = 0; it < 16; ++it) {
        int i = tid + it * 256;
        int f = i >> 5, k = i & 31;
        ob[(size_t)f * KK + k] = tile[k * 129 + f];
    }
}

// --------------------------------------------------------------------------
extern "C" void kernel_launch(void* const* d_in, const int* in_sizes, int n_in,
                              void* d_out, int out_size) {
    const float* node_embs = (const float*)d_in[0];
    const float* mask      = (const float*)d_in[1];
    const float* h_t       = (const float*)d_in[2];
    const float* W_map     = (const float*)d_in[3];
    const float* b_map     = (const float*)d_in[4];
    float* out    = (float*)d_out;
    float* policy = out + (size_t)BB * FF * KK;   // outputs: [B,F,K] then [B]

    k1_scorer<<<BB, FF>>>(h_t, W_map, b_map);
    k2_scores<<<dim3(BB, GG / 64), 256>>>(node_embs, mask);
    k3_topk<<<BB, 512>>>(policy);
    k4_gather<<<dim3(BB, 4), 256>>>(node_embs, out);
}

// round 3
// speedup vs baseline: 1.5699x; 1.1271x over previous
#include <cuda_runtime.h>
#include <math.h>

#define BB  256
#define GG  2048
#define FF  128
#define RNN 512
#define KK  128

// Scratch (no allocation allowed) ------------------------------------------
__device__ float g_scorer[BB * FF];   // scorer / ||scorer||, per batch
__device__ float g_scores[BB * GG];   // scores (incl. mask)
__device__ float g_tvals [BB * KK];   // tanh(topk values), sorted desc
__device__ int   g_tidx  [BB * KK];   // topk indices, sorted desc

// --------------------------------------------------------------------------
// K1: scorer[b,f] = tanh(h_t[b,:] @ W[:,f] + bias[f]) / ||tanh(...)||_2
// --------------------------------------------------------------------------
__global__ void k1_scorer(const float* __restrict__ h_t,
                          const float* __restrict__ W,
                          const float* __restrict__ bmap) {
    int b = blockIdx.x, f = threadIdx.x;     // 128 threads
    __shared__ float h[RNN];
    __shared__ float red[FF];
    for (int i = f; i < RNN; i += FF) h[i] = h_t[b * RNN + i];
    __syncthreads();
    float acc = bmap[f];
#pragma unroll 8
    for (int r = 0; r < RNN; ++r) acc = fmaf(h[r], W[r * FF + f], acc);
    float s = tanhf(acc);
    red[f] = s * s;
    __syncthreads();
    for (int o = FF / 2; o > 0; o >>= 1) {
        if (f < o) red[f] += red[f + o];
        __syncthreads();
    }
    g_scorer[b * FF + f] = s * rsqrtf(red[0]);
}

// --------------------------------------------------------------------------
// K2: scores[b,g] = node_embs[b,g,:] . scorer[b,:] + mask[b,g]
//     warp per row, 4 independent rows in flight per warp (HBM-floor bound)
// --------------------------------------------------------------------------
__global__ void k2_scores(const float* __restrict__ ne,
                          const float* __restrict__ mask) {
    int b = blockIdx.x;
    int gbase = blockIdx.y * 64;             // 64 g-rows per block
    __shared__ float4 sc[FF / 4];
    int tid = threadIdx.x;                   // 256 threads
    if (tid < FF / 4)
        sc[tid] = reinterpret_cast<const float4*>(g_scorer + b * FF)[tid];
    __syncthreads();
    int warp = tid >> 5, lane = tid & 31;
    float4 s = sc[lane];
    const float4* base = reinterpret_cast<const float4*>(ne) + (size_t)b * GG * (FF / 4);
    int g0 = gbase + warp * 8;
#pragma unroll
    for (int half = 0; half < 2; ++half) {
        float d0, d1, d2, d3;
        {
            float4 v0 = base[(size_t)(g0 + half * 4 + 0) * (FF / 4) + lane];
            float4 v1 = base[(size_t)(g0 + half * 4 + 1) * (FF / 4) + lane];
            float4 v2 = base[(size_t)(g0 + half * 4 + 2) * (FF / 4) + lane];
            float4 v3 = base[(size_t)(g0 + half * 4 + 3) * (FF / 4) + lane];
            d0 = v0.x * s.x + v0.y * s.y + v0.z * s.z + v0.w * s.w;
            d1 = v1.x * s.x + v1.y * s.y + v1.z * s.z + v1.w * s.w;
            d2 = v2.x * s.x + v2.y * s.y + v2.z * s.z + v2.w * s.w;
            d3 = v3.x * s.x + v3.y * s.y + v3.z * s.z + v3.w * s.w;
        }
#pragma unroll
        for (int o = 16; o > 0; o >>= 1) {
            d0 += __shfl_xor_sync(0xffffffffu, d0, o);
            d1 += __shfl_xor_sync(0xffffffffu, d1, o);
            d2 += __shfl_xor_sync(0xffffffffu, d2, o);
            d3 += __shfl_xor_sync(0xffffffffu, d3, o);
        }
        if (lane == 0) {
            int g = g0 + half * 4;
            const float* mb = mask + b * GG + g;
            float* ob = g_scores + b * GG + g;
            ob[0] = d0 + mb[0];
            ob[1] = d1 + mb[1];
            ob[2] = d2 + mb[2];
            ob[3] = d3 + mb[3];
        }
    }
}

// --------------------------------------------------------------------------
// K3: per-batch logsumexp + 32-bit radix-select (4x8-bit passes, warp-shfl
//     suffix scan) + rank-by-counting emit of top-128. ~20 barriers total.
// --------------------------------------------------------------------------
__device__ __forceinline__ unsigned f2u(float f) {
    unsigned u = __float_as_uint(f);
    return (u & 0x80000000u) ? ~u : (u | 0x80000000u);
}
__device__ __forceinline__ float u2f(unsigned u) {
    unsigned b = (u & 0x80000000u) ? (u & 0x7FFFFFFFu) : ~u;
    return __uint_as_float(b);
}

__global__ void k3_topk(float* __restrict__ policy_out) {
    const unsigned FULL = 0xffffffffu;
    int b = blockIdx.x, tid = threadIdx.x;   // 512 threads, 16 warps
    int lane = tid & 31, warp = tid >> 5;
    __shared__ float rbuf[16];
    __shared__ unsigned hist[256];
    __shared__ unsigned long long top[256];
    __shared__ unsigned sel_d, sel_sub, cnt_;
    __shared__ float s_smax, s_lse;

    // load 4 scores / thread (coalesced)
    float v[4];
    unsigned u[4];
#pragma unroll
    for (int j = 0; j < 4; ++j) v[j] = g_scores[b * GG + tid + j * 512];

    // ---- max (warp shuffles + 16-slot smem) ----
    float m = fmaxf(fmaxf(v[0], v[1]), fmaxf(v[2], v[3]));
#pragma unroll
    for (int o = 16; o > 0; o >>= 1) m = fmaxf(m, __shfl_xor_sync(FULL, m, o));
    if (lane == 0) rbuf[warp] = m;
    __syncthreads();
    if (tid < 32) {
        float x = (tid < 16) ? rbuf[tid] : -INFINITY;
#pragma unroll
        for (int o = 8; o > 0; o >>= 1) x = fmaxf(x, __shfl_xor_sync(FULL, x, o));
        if (tid == 0) s_smax = x;
    }
    __syncthreads();
    float smax = s_smax;

    // ---- sum exp ----
    float sum = expf(v[0] - smax) + expf(v[1] - smax) +
                expf(v[2] - smax) + expf(v[3] - smax);
#pragma unroll
    for (int o = 16; o > 0; o >>= 1) sum += __shfl_xor_sync(FULL, sum, o);
    if (lane == 0) rbuf[warp] = sum;
    __syncthreads();
    if (tid < 32) {
        float x = (tid < 16) ? rbuf[tid] : 0.f;
#pragma unroll
        for (int o = 8; o > 0; o >>= 1) x += __shfl_xor_sync(FULL, x, o);
        if (tid == 0) s_lse = smax + logf(x);
    }

#pragma unroll
    for (int j = 0; j < 4; ++j) u[j] = f2u(v[j]);

    // ---- radix select over 32-bit sortable value, 4 passes ----
    unsigned prefix = 0, kneed = KK;
    for (int shift = 24; shift >= 0; shift -= 8) {
        unsigned maskhi = (shift == 24) ? 0u : (0xFFFFFFFFu << (shift + 8));
        __syncthreads();
        if (tid < 256) hist[tid] = 0;
        __syncthreads();
#pragma unroll
        for (int j = 0; j < 4; ++j)
            if ((u[j] & maskhi) == prefix)
                atomicAdd(&hist[(u[j] >> shift) & 0xFFu], 1u);
        __syncthreads();
        // single-warp suffix scan of 256 bins (8 bins per lane, shfl across lanes)
        if (tid < 32) {
            unsigned hv[8], t = 0;
#pragma unroll
            for (int q = 0; q < 8; ++q) { hv[q] = hist[tid * 8 + q]; t += hv[q]; }
            unsigned x = t;
#pragma unroll
            for (int o = 1; o < 32; o <<= 1) {
                unsigned y = __shfl_down_sync(FULL, x, o);
                if (tid + o < 32) x += y;
            }
            unsigned run = x - t;   // suffix of lanes above
#pragma unroll
            for (int q = 7; q >= 0; --q) { run += hv[q]; hist[tid * 8 + q] = run; }
        }
        __syncthreads();
        if (tid < 256) {
            unsigned h = hist[tid];
            unsigned hn = (tid == 255) ? 0u : hist[tid + 1];
            if (h >= kneed && hn < kneed) { sel_d = (unsigned)tid; sel_sub = hn; }
        }
        __syncthreads();
        prefix |= sel_d << shift;
        kneed -= sel_sub;
    }

    // ---- collect keys with value >= threshold (>=128, ==128 when distinct) ----
    if (tid == 0) cnt_ = 0;
    __syncthreads();
#pragma unroll
    for (int j = 0; j < 4; ++j) {
        if (u[j] >= prefix) {
            unsigned p = atomicAdd(&cnt_, 1u);
            if (p < 256)
                top[p] = ((unsigned long long)u[j] << 32) |
                         (unsigned)(~(unsigned)(tid + j * 512));
        }
    }
    __syncthreads();
    unsigned n = cnt_ < 256u ? cnt_ : 256u;

    // ---- rank by counting (value desc, index asc), emit directly ----
    float contrib = 0.f;
    if (tid < (int)n) {
        unsigned long long key = top[tid];
        unsigned r = 0;
        for (unsigned jj = 0; jj < n; ++jj) r += (top[jj] > key);
        if (r < KK) {
            float val = u2f((unsigned)(key >> 32));
            g_tvals[b * KK + r] = tanhf(val);
            g_tidx [b * KK + r] = (int)(~(unsigned)key);
            contrib = val;
        }
    }
    // deterministic block sum of contributions
#pragma unroll
    for (int o = 16; o > 0; o >>= 1) contrib += __shfl_xor_sync(FULL, contrib, o);
    __syncthreads();
    if (lane == 0) rbuf[warp] = contrib;
    __syncthreads();
    if (tid < 32) {
        float x = (tid < 16) ? rbuf[tid] : 0.f;
#pragma unroll
        for (int o = 8; o > 0; o >>= 1) x += __shfl_xor_sync(FULL, x, o);
        if (tid == 0) policy_out[b] = x * (1.0f / KK) - s_lse;
    }
}

// --------------------------------------------------------------------------
// K4: out[b,f,k] = node_embs[b, idx[b,k], f] * tanh(val[b,k])
//     4 blocks/batch, LDG.128 gather, padded smem transpose, STG.128 writes
// --------------------------------------------------------------------------
__global__ void k4_gather(const float* __restrict__ ne, float* __restrict__ out) {
    int b = blockIdx.x, kq = blockIdx.y;     // quarter index 0..3
    int tid = threadIdx.x;                   // 256 threads
    __shared__ float tile[32 * 129];
    __shared__ float tv[32];
    __shared__ int   ti[32];
    if (tid < 32) {
        tv[tid] = g_tvals[b * KK + kq * 32 + tid];
        ti[tid] = g_tidx [b * KK + kq * 32 + tid];
    }
    __syncthreads();
    const float4* base = reinterpret_cast<const float4*>(ne) + (size_t)b * GG * (FF / 4);
    float* ob = out + (size_t)b * FF * KK + kq * 32;
    // load: 32 rows x 32 float4 (coalesced 512B per row), scale, STS
#pragma unroll
    for (int it = 0; it < 4; ++it) {
        int i = tid + it * 256;              // 0..1023
        int k = i >> 5, c = i & 31;
        float4 v = base[(size_t)ti[k] * (FF / 4) + c];
        float s = tv[k];
        float* t = tile + k * 129 + c * 4;
        t[0] = v.x * s; t[1] = v.y * s; t[2] = v.z * s; t[3] = v.w * s;
    }
    __syncthreads();
    // write transposed: 4 conflict-free LDS + one STG.128 per thread-iter
#pragma unroll
    for (int it = 0; it < 4; ++it) {
        int i = tid + it * 256;              // 0..1023
        int f = i >> 3, q = i & 7;
        int k = q * 4;
        float4 w;
        w.x = tile[(k + 0) * 129 + f];
        w.y = tile[(k + 1) * 129 + f];
        w.z = tile[(k + 2) * 129 + f];
        w.w = tile[(k + 3) * 129 + f];
        *reinterpret_cast<float4*>(ob + (size_t)f * KK + k) = w;
    }
}

// --------------------------------------------------------------------------
extern "C" void kernel_launch(void* const* d_in, const int* in_sizes, int n_in,
                              void* d_out, int out_size) {
    const float* node_embs = (const float*)d_in[0];
    const float* mask      = (const float*)d_in[1];
    const float* h_t       = (const float*)d_in[2];
    const float* W_map     = (const float*)d_in[3];
    const float* b_map     = (const float*)d_in[4];
    float* out    = (float*)d_out;
    float* policy = out + (size_t)BB * FF * KK;   // outputs: [B,F,K] then [B]

    k1_scorer<<<BB, FF>>>(h_t, W_map, b_map);
    k2_scores<<<dim3(BB, GG / 64), 256>>>(node_embs, mask);
    k3_topk<<<BB, 512>>>(policy);
    k4_gather<<<dim3(BB, 4), 256>>>(node_embs, out);
}

// round 4
// speedup vs baseline: 2.0155x; 1.2838x over previous
#include <cuda_runtime.h>
#include <math.h>

#define BB  256
#define GG  2048
#define FF  128
#define RNN 512
#define KK  128

// Scratch (no allocation allowed) ------------------------------------------
__device__ float g_scorer[BB * FF];   // scorer / ||scorer||, per batch
__device__ float g_scores[BB * GG];   // scores (incl. mask)
__device__ float g_tvals [BB * KK];   // tanh(topk values), sorted desc
__device__ int   g_tidx  [BB * KK];   // topk indices, sorted desc

// --------------------------------------------------------------------------
// K1: scorer[b,f] = tanh(h_t[b,:] @ W[:,f] + bias[f]) / ||tanh||
//     4 batches per block, W staged through smem in 64-row chunks.
// --------------------------------------------------------------------------
__global__ void k1_scorer(const float* __restrict__ h_t,
                          const float* __restrict__ W,
                          const float* __restrict__ bmap) {
    int tid = threadIdx.x;               // 512
    int bq = tid >> 7, f = tid & 127;    // batch-quadrant, feature
    int b0 = blockIdx.x * 4;
    __shared__ float Ws[64 * 128];       // 32KB chunk of W
    __shared__ float hs[4 * RNN];        // 8KB: h for 4 batches
    __shared__ float red2[16];
    for (int i = tid; i < 4 * RNN; i += 512)
        hs[i] = h_t[(b0 + (i >> 9)) * RNN + (i & 511)];
    float acc = bmap[f];
    for (int c = 0; c < RNN / 64; ++c) {
        __syncthreads();
        for (int i = tid; i < 64 * 128; i += 512)
            Ws[i] = W[(c * 64 + (i >> 7)) * 128 + (i & 127)];
        __syncthreads();
        const float* hb = hs + bq * RNN + c * 64;
#pragma unroll
        for (int r = 0; r < 64; ++r) acc = fmaf(hb[r], Ws[r * 128 + f], acc);
    }
    float s = tanhf(acc);
    float q = s * s;
#pragma unroll
    for (int o = 16; o > 0; o >>= 1) q += __shfl_xor_sync(0xffffffffu, q, o);
    int warp = tid >> 5, lane = tid & 31;
    if (lane == 0) red2[warp] = q;
    __syncthreads();
    float nrm = red2[bq * 4] + red2[bq * 4 + 1] + red2[bq * 4 + 2] + red2[bq * 4 + 3];
    g_scorer[(b0 + bq) * FF + f] = s * rsqrtf(nrm);
}

// --------------------------------------------------------------------------
// K2: scores[b,g] = node_embs[b,g,:] . scorer[b,:] + mask[b,g]
//     warp per row, 8 independent rows in flight, streaming loads
// --------------------------------------------------------------------------
__global__ void k2_scores(const float* __restrict__ ne,
                          const float* __restrict__ mask) {
    int b = blockIdx.x;
    int gbase = blockIdx.y * 64;             // 64 g-rows per block
    __shared__ float4 sc[FF / 4];
    int tid = threadIdx.x;                   // 256 threads
    if (tid < FF / 4)
        sc[tid] = reinterpret_cast<const float4*>(g_scorer + b * FF)[tid];
    __syncthreads();
    int warp = tid >> 5, lane = tid & 31;
    float4 s = sc[lane];
    const float4* base = reinterpret_cast<const float4*>(ne) + (size_t)b * GG * (FF / 4);
    int g0 = gbase + warp * 8;
    float d[8];
#pragma unroll
    for (int j = 0; j < 8; ++j) {
        float4 v = __ldcs(base + (size_t)(g0 + j) * (FF / 4) + lane);
        d[j] = v.x * s.x + v.y * s.y + v.z * s.z + v.w * s.w;
    }
#pragma unroll
    for (int o = 16; o > 0; o >>= 1) {
#pragma unroll
        for (int j = 0; j < 8; ++j) d[j] += __shfl_xor_sync(0xffffffffu, d[j], o);
    }
    if (lane == 0) {
        const float4* mb = reinterpret_cast<const float4*>(mask + b * GG + g0);
        float4* ob = reinterpret_cast<float4*>(g_scores + b * GG + g0);
        float4 m0 = mb[0], m1 = mb[1];
        ob[0] = make_float4(d[0] + m0.x, d[1] + m0.y, d[2] + m0.z, d[3] + m0.w);
        ob[1] = make_float4(d[4] + m1.x, d[5] + m1.y, d[6] + m1.z, d[7] + m1.w);
    }
}

// --------------------------------------------------------------------------
// K3: 32-bit radix-select top-128 + rank-by-count emit + logsumexp
//     (max taken from rank-0 key; no separate max pass)
// --------------------------------------------------------------------------
__device__ __forceinline__ unsigned f2u(float f) {
    unsigned u = __float_as_uint(f);
    return (u & 0x80000000u) ? ~u : (u | 0x80000000u);
}
__device__ __forceinline__ float u2f(unsigned u) {
    unsigned b = (u & 0x80000000u) ? (u & 0x7FFFFFFFu) : ~u;
    return __uint_as_float(b);
}

__global__ void k3_topk(float* __restrict__ policy_out) {
    const unsigned FULL = 0xffffffffu;
    int b = blockIdx.x, tid = threadIdx.x;   // 512 threads, 16 warps
    int lane = tid & 31, warp = tid >> 5;
    __shared__ float rbuf[16];
    __shared__ unsigned hist[256];
    __shared__ unsigned long long top[256];
    __shared__ unsigned sel_d, sel_sub, cnt_;
    __shared__ float s_smax;

    // load 4 scores / thread (coalesced)
    float v[4];
    unsigned u[4];
#pragma unroll
    for (int j = 0; j < 4; ++j) {
        v[j] = g_scores[b * GG + tid + j * 512];
        u[j] = f2u(v[j]);
    }

    // ---- radix select over 32-bit sortable value, 4x8-bit passes ----
    unsigned prefix = 0, kneed = KK;
    for (int shift = 24; shift >= 0; shift -= 8) {
        unsigned maskhi = (shift == 24) ? 0u : (0xFFFFFFFFu << (shift + 8));
        __syncthreads();
        if (tid < 256) hist[tid] = 0;
        __syncthreads();
#pragma unroll
        for (int j = 0; j < 4; ++j)
            if ((u[j] & maskhi) == prefix)
                atomicAdd(&hist[(u[j] >> shift) & 0xFFu], 1u);
        __syncthreads();
        // single-warp suffix scan of 256 bins
        if (tid < 32) {
            unsigned hv[8], t = 0;
#pragma unroll
            for (int q = 0; q < 8; ++q) { hv[q] = hist[tid * 8 + q]; t += hv[q]; }
            unsigned x = t;
#pragma unroll
            for (int o = 1; o < 32; o <<= 1) {
                unsigned y = __shfl_down_sync(FULL, x, o);
                if (tid + o < 32) x += y;
            }
            unsigned run = x - t;   // suffix of lanes above
#pragma unroll
            for (int q = 7; q >= 0; --q) { run += hv[q]; hist[tid * 8 + q] = run; }
        }
        __syncthreads();
        if (tid < 256) {
            unsigned h = hist[tid];
            unsigned hn = (tid == 255) ? 0u : hist[tid + 1];
            if (h >= kneed && hn < kneed) { sel_d = (unsigned)tid; sel_sub = hn; }
        }
        __syncthreads();
        prefix |= sel_d << shift;
        kneed -= sel_sub;
    }

    // ---- collect keys with value >= threshold ----
    if (tid == 0) cnt_ = 0;
    __syncthreads();
#pragma unroll
    for (int j = 0; j < 4; ++j) {
        if (u[j] >= prefix) {
            unsigned p = atomicAdd(&cnt_, 1u);
            if (p < 256)
                top[p] = ((unsigned long long)u[j] << 32) |
                         (unsigned)(~(unsigned)(tid + j * 512));
        }
    }
    __syncthreads();
    unsigned n = cnt_ < 256u ? cnt_ : 256u;

    // ---- rank by counting (value desc, index asc), emit directly ----
    float contrib = 0.f;
    if (tid < (int)n) {
        unsigned long long key = top[tid];
        unsigned r = 0;
        for (unsigned jj = 0; jj < n; ++jj) r += (top[jj] > key);
        if (r < KK) {
            float val = u2f((unsigned)(key >> 32));
            g_tvals[b * KK + r] = tanhf(val);
            g_tidx [b * KK + r] = (int)(~(unsigned)key);
            contrib = val;
            if (r == 0) s_smax = val;    // global max score
        }
    }
    // block sum of top values
#pragma unroll
    for (int o = 16; o > 0; o >>= 1) contrib += __shfl_xor_sync(FULL, contrib, o);
    if (lane == 0) rbuf[warp] = contrib;
    __syncthreads();
    float sumtop = 0.f;
    if (tid == 0) {
#pragma unroll
        for (int w = 0; w < 16; ++w) sumtop += rbuf[w];
    }
    float smax = s_smax;
    __syncthreads();

    // ---- sum exp (registers) ----
    float sum = expf(v[0] - smax) + expf(v[1] - smax) +
                expf(v[2] - smax) + expf(v[3] - smax);
#pragma unroll
    for (int o = 16; o > 0; o >>= 1) sum += __shfl_xor_sync(FULL, sum, o);
    if (lane == 0) rbuf[warp] = sum;
    __syncthreads();
    if (tid == 0) {
        float x = 0.f;
#pragma unroll
        for (int w = 0; w < 16; ++w) x += rbuf[w];
        policy_out[b] = sumtop * (1.0f / KK) - (smax + logf(x));
    }
}

// --------------------------------------------------------------------------
// K4: out[b,f,k] = node_embs[b, idx[b,k], f] * tanh(val[b,k])
//     8 blocks/batch (16 k-rows), LDG.128 gather, padded transpose, STG.128
// --------------------------------------------------------------------------
__global__ void k4_gather(const float* __restrict__ ne, float* __restrict__ out) {
    int b = blockIdx.x, kq = blockIdx.y;     // eighth index 0..7
    int tid = threadIdx.x;                   // 256 threads
    __shared__ float tile[16 * 129];
    __shared__ float tv[16];
    __shared__ int   ti[16];
    if (tid < 16) {
        tv[tid] = g_tvals[b * KK + kq * 16 + tid];
        ti[tid] = g_tidx [b * KK + kq * 16 + tid];
    }
    __syncthreads();
    const float4* base = reinterpret_cast<const float4*>(ne) + (size_t)b * GG * (FF / 4);
    float* ob = out + (size_t)b * FF * KK + kq * 16;
    // load: 16 rows x 32 float4 (coalesced 512B per row), scale, STS
#pragma unroll
    for (int it = 0; it < 2; ++it) {
        int i = tid + it * 256;              // 0..511
        int k = i >> 5, c = i & 31;
        float4 v = base[(size_t)ti[k] * (FF / 4) + c];
        float s = tv[k];
        float* t = tile + k * 129 + c * 4;
        t[0] = v.x * s; t[1] = v.y * s; t[2] = v.z * s; t[3] = v.w * s;
    }
    __syncthreads();
    // write transposed: 4 LDS + one STG.128 per thread-iter
#pragma unroll
    for (int it = 0; it < 2; ++it) {
        int i = tid + it * 256;              // 0..511
        int f = i >> 2, q = i & 3;
        int k = q * 4;
        float4 w;
        w.x = tile[(k + 0) * 129 + f];
        w.y = tile[(k + 1) * 129 + f];
        w.z = tile[(k + 2) * 129 + f];
        w.w = tile[(k + 3) * 129 + f];
        *reinterpret_cast<float4*>(ob + (size_t)f * KK + k) = w;
    }
}

// --------------------------------------------------------------------------
extern "C" void kernel_launch(void* const* d_in, const int* in_sizes, int n_in,
                              void* d_out, int out_size) {
    const float* node_embs = (const float*)d_in[0];
    const float* mask      = (const float*)d_in[1];
    const float* h_t       = (const float*)d_in[2];
    const float* W_map     = (const float*)d_in[3];
    const float* b_map     = (const float*)d_in[4];
    float* out    = (float*)d_out;
    float* policy = out + (size_t)BB * FF * KK;   // outputs: [B,F,K] then [B]

    k1_scorer<<<BB / 4, 512>>>(h_t, W_map, b_map);
    k2_scores<<<dim3(BB, GG / 64), 256>>>(node_embs, mask);
    k3_topk<<<BB, 512>>>(policy);
    k4_gather<<<dim3(BB, 8), 256>>>(node_embs, out);
}